// round 9
// baseline (speedup 1.0000x reference)
#include <cuda_runtime.h>
#include <math.h>

#define B_  64
#define C_  512
#define HW_ 4096      // 64*64
#define E_  16
#define K_  4

#define ROWS_PER_BLK 8                      // 8 warps/block, 1 row/warp
#define BLKS_PER_B   (C_ / ROWS_PER_BLK)    // 64 blocks per batch

// Accumulators for the two matvecs (zero-init; tail resets them each call)
__device__ float g_h [B_ * E_];
__device__ float g_nz[B_ * E_];
__device__ int   g_count[B_];

// ---------------------------------------------------------------------------
// Cold tail: scalar epilogue for one batch. No dots, no weight traffic —
// those were accumulated by the pool warps. __noinline__ keeps its registers
// out of the hot loop's budget.
// ---------------------------------------------------------------------------
__device__ __noinline__ void gate_tail(int b,
                                       const float* __restrict__ b0,
                                       const float* __restrict__ b1,
                                       float* __restrict__ out) {
    if (threadIdx.x != 0) return;

    float h[E_], nz[E_];
#pragma unroll
    for (int i = 0; i < E_; i++) {
        float hv = g_h[b * E_ + i] + b0[i];
        h[i] = (hv >= 0.0f) ? hv : 0.2f * hv;                  // LeakyReLU(0.2)
        float z = g_nz[b * E_ + i] + b1[i];
        nz[i] = fmaxf(z, 0.0f) + log1pf(expf(-fabsf(z)));      // softplus
        // reset accumulators for the next graph replay
        g_h[b * E_ + i]  = 0.0f;
        g_nz[b * E_ + i] = 0.0f;
    }
    g_count[b] = 0;

    float mu = 0.0f;
#pragma unroll
    for (int i = 0; i < E_; i++) mu += nz[i];
    mu *= (1.0f / E_);

    float var = 0.0f;
#pragma unroll
    for (int i = 0; i < E_; i++) { float d = nz[i] - mu; var += d * d; }
    float sd = sqrtf(var * (1.0f / (E_ - 1)));                 // ddof=1

    float score[E_];
#pragma unroll
    for (int i = 0; i < E_; i++) score[i] = h[i] + (nz[i] - mu) / sd;

    // top-K; strict '>' = first-occurrence tie-break like jax.lax.top_k
    bool sel[E_];
#pragma unroll
    for (int i = 0; i < E_; i++) sel[i] = false;
    for (int k = 0; k < K_; k++) {
        int   best = -1;
        float bv   = -INFINITY;
#pragma unroll
        for (int i = 0; i < E_; i++) {
            if (!sel[i] && score[i] > bv) { bv = score[i]; best = i; }
        }
        sel[best] = true;
    }

    float mh = -INFINITY;
#pragma unroll
    for (int i = 0; i < E_; i++) if (sel[i]) mh = fmaxf(mh, h[i]);
    float s = 0.0f;
    float g[E_];
#pragma unroll
    for (int i = 0; i < E_; i++) {
        g[i] = sel[i] ? expf(h[i] - mh) : 0.0f;
        s += g[i];
    }
    float inv = 1.0f / s;
#pragma unroll
    for (int i = 0; i < E_; i++) out[b * E_ + i] = g[i] * inv;
}

// ---------------------------------------------------------------------------
// Fused kernel. One warp per (b,c) row: pool the row, then every lane
// contributes one expert's partial dot via atomicAdd (lanes 0-15 -> W0/g_h,
// lanes 16-31 -> W1/g_nz). Last block per batch runs the scalar tail.
// No launch_bounds: the pool loop keeps its natural register/load window.
// ---------------------------------------------------------------------------
__global__ void fused_gate_kernel(
    const float* __restrict__ x,
    const float* __restrict__ W0, const float* __restrict__ b0,
    const float* __restrict__ W1, const float* __restrict__ b1,
    float* __restrict__ out) {

    const int tid  = threadIdx.x;
    const int wid  = tid >> 5;
    const int lane = tid & 31;
    const int row  = blockIdx.x * ROWS_PER_BLK + wid;   // (b,c)
    const int b    = blockIdx.x / BLKS_PER_B;
    const int c    = row & (C_ - 1);

    __shared__ int sh_last;

    // ---------------- pool: max + mean over 4096 contiguous floats ----------
    const float4* __restrict__ p =
        reinterpret_cast<const float4*>(x + (size_t)row * HW_);
    float mx0 = -INFINITY, mx1 = -INFINITY;
    float sm0 = 0.0f, sm1 = 0.0f;
#pragma unroll
    for (int i = 0; i < HW_ / 4 / 32; i += 2) {   // 32 float4/lane, 2 chains
        float4 a = p[i * 32 + lane];
        float4 d = p[(i + 1) * 32 + lane];
        mx0 = fmaxf(mx0, fmaxf(fmaxf(a.x, a.y), fmaxf(a.z, a.w)));
        sm0 += (a.x + a.y) + (a.z + a.w);
        mx1 = fmaxf(mx1, fmaxf(fmaxf(d.x, d.y), fmaxf(d.z, d.w)));
        sm1 += (d.x + d.y) + (d.z + d.w);
    }
    float mx = fmaxf(mx0, mx1);
    float sm = sm0 + sm1;
#pragma unroll
    for (int o = 16; o; o >>= 1) {      // butterfly: result lands in ALL lanes
        mx = fmaxf(mx, __shfl_xor_sync(0xffffffffu, mx, o));
        sm += __shfl_xor_sync(0xffffffffu, sm, o);
    }
    const float pooled = mx + sm * (1.0f / HW_);

    // ---------------- distribute partial dots: 1 load + 1 atomic per lane ---
    {
        const int e = lane & 15;
        const float w = (lane < 16) ? W0[e * C_ + c] : W1[e * C_ + c];
        float* dst = (lane < 16) ? &g_h[b * E_ + e] : &g_nz[b * E_ + e];
        atomicAdd(dst, pooled * w);
    }

    // ---------------- block-level completion protocol -----------------------
    __syncthreads();
    if (tid == 0) {
        __threadfence();                  // release our atomics
        sh_last = (atomicAdd(&g_count[b], 1) == BLKS_PER_B - 1);
    }
    __syncthreads();
    if (!sh_last) return;
    __threadfence();                      // acquire all batch-b contributions

    gate_tail(b, b0, b1, out);
}

// ---------------------------------------------------------------------------
extern "C" void kernel_launch(void* const* d_in, const int* in_sizes, int n_in,
                              void* d_out, int out_size) {
    const float* x  = (const float*)d_in[0];
    const float* W0 = (const float*)d_in[1];
    const float* b0 = (const float*)d_in[2];
    const float* W1 = (const float*)d_in[3];
    const float* b1 = (const float*)d_in[4];
    float* out = (float*)d_out;

    fused_gate_kernel<<<(B_ * C_) / ROWS_PER_BLK, 256>>>(x, W0, b0, W1, b1, out);
}

// round 10
// speedup vs baseline: 1.5462x; 1.5462x over previous
#include <cuda_runtime.h>
#include <math.h>

#define B_  64
#define C_  512
#define HW_ 4096      // 64*64
#define E_  16
#define K_  4

#define ROWS_PER_BLK 8                      // 8 warps/block, 1 row/warp
#define BLKS_PER_B   (C_ / ROWS_PER_BLK)    // 64 pool blocks per batch

__device__ float g_pooled[B_ * C_];
__device__ int   g_count[B_];               // zero-init; gate resets per replay

// ---------------------------------------------------------------------------
// Pool kernel (champion structure, natural registers). Adds only a per-block
// completion signal. Trigger fires at start so the PDL secondary co-schedules.
// ---------------------------------------------------------------------------
__global__ __launch_bounds__(256) void pool_kernel(const float* __restrict__ x) {
    cudaTriggerProgrammaticLaunchCompletion();

    const int tid  = threadIdx.x;
    const int wid  = tid >> 5;
    const int lane = tid & 31;
    const int row  = blockIdx.x * ROWS_PER_BLK + wid;   // (b,c) row
    const int b    = blockIdx.x / BLKS_PER_B;

    const float4* __restrict__ p =
        reinterpret_cast<const float4*>(x + (size_t)row * HW_);

    float mx0 = -INFINITY, mx1 = -INFINITY;
    float sm0 = 0.0f, sm1 = 0.0f;
#pragma unroll
    for (int i = 0; i < HW_ / 4 / 32; i += 2) {   // 32 float4 per lane, 2 chains
        float4 a = p[i * 32 + lane];
        float4 c = p[(i + 1) * 32 + lane];
        mx0 = fmaxf(mx0, fmaxf(fmaxf(a.x, a.y), fmaxf(a.z, a.w)));
        sm0 += (a.x + a.y) + (a.z + a.w);
        mx1 = fmaxf(mx1, fmaxf(fmaxf(c.x, c.y), fmaxf(c.z, c.w)));
        sm1 += (c.x + c.y) + (c.z + c.w);
    }
    float mx = fmaxf(mx0, mx1);
    float sm = sm0 + sm1;
#pragma unroll
    for (int o = 16; o; o >>= 1) {
        mx = fmaxf(mx, __shfl_xor_sync(0xffffffffu, mx, o));
        sm += __shfl_xor_sync(0xffffffffu, sm, o);
    }
    if (lane == 0) g_pooled[row] = mx + sm * (1.0f / HW_);

    __syncthreads();                          // block's 8 rows are stored
    if (tid == 0) {
        __threadfence();                      // release g_pooled writes
        atomicAdd(&g_count[b], 1);
    }
}

// ---------------------------------------------------------------------------
// Gate kernel (PDL secondary). Launches while pool runs: loads weights into
// registers immediately (hides DRAM-cold latency under pooling), then spins
// on its batch's counter and finishes ~as soon as that batch's rows are done.
// 64 blocks x 512 threads; warp e handles expert e.
// ---------------------------------------------------------------------------
__global__ __launch_bounds__(512) void gate_kernel(const float* __restrict__ W0,
                                                   const float* __restrict__ b0,
                                                   const float* __restrict__ W1,
                                                   const float* __restrict__ b1,
                                                   float* __restrict__ out) {
    const int b    = blockIdx.x;
    const int tid  = threadIdx.x;
    const int e    = tid >> 5;     // expert = warp id (0..15)
    const int lane = tid & 31;

    __shared__ float sh_h[E_];
    __shared__ float sh_noise[E_];

    // -------- prologue: overlapped with pool_kernel execution ---------------
    const float4* __restrict__ w0p =
        reinterpret_cast<const float4*>(W0 + e * C_) + lane;
    const float4* __restrict__ w1p =
        reinterpret_cast<const float4*>(W1 + e * C_) + lane;
    float4 w0r[4], w1r[4];
#pragma unroll
    for (int i = 0; i < 4; i++) w0r[i] = w0p[i * 32];
#pragma unroll
    for (int i = 0; i < 4; i++) w1r[i] = w1p[i * 32];
    const float bias0 = b0[e];
    const float bias1 = b1[e];

    // -------- wait for THIS batch's pool blocks (per-batch, not grid-wide) --
    if (tid == 0) {
        volatile int* cnt = g_count + b;
        while (*cnt < BLKS_PER_B) __nanosleep(64);
        __threadfence();                      // acquire batch-b g_pooled writes
    }
    __syncthreads();

    const float4* __restrict__ prow =
        reinterpret_cast<const float4*>(g_pooled + b * C_) + lane;
    float d0 = 0.0f, d1 = 0.0f;
#pragma unroll
    for (int i = 0; i < 4; i++) {
        float4 pv = prow[i * 32];
        d0 = fmaf(pv.x, w0r[i].x, d0); d0 = fmaf(pv.y, w0r[i].y, d0);
        d0 = fmaf(pv.z, w0r[i].z, d0); d0 = fmaf(pv.w, w0r[i].w, d0);
        d1 = fmaf(pv.x, w1r[i].x, d1); d1 = fmaf(pv.y, w1r[i].y, d1);
        d1 = fmaf(pv.z, w1r[i].z, d1); d1 = fmaf(pv.w, w1r[i].w, d1);
    }
#pragma unroll
    for (int o = 16; o; o >>= 1) {
        d0 += __shfl_xor_sync(0xffffffffu, d0, o);
        d1 += __shfl_xor_sync(0xffffffffu, d1, o);
    }
    if (lane == 0) {
        float hv = d0 + bias0;
        sh_h[e] = (hv >= 0.0f) ? hv : 0.2f * hv;          // LeakyReLU(0.2)
        float z = d1 + bias1;
        sh_noise[e] = fmaxf(z, 0.0f) + log1pf(expf(-fabsf(z)));   // softplus
    }
    __syncthreads();

    // -------- scalar epilogue on thread 0 -----------------------------------
    if (tid == 0) {
        float h[E_], nz[E_];
#pragma unroll
        for (int i = 0; i < E_; i++) { h[i] = sh_h[i]; nz[i] = sh_noise[i]; }

        float mu = 0.0f;
#pragma unroll
        for (int i = 0; i < E_; i++) mu += nz[i];
        mu *= (1.0f / E_);

        float var = 0.0f;
#pragma unroll
        for (int i = 0; i < E_; i++) { float d = nz[i] - mu; var += d * d; }
        float sd = sqrtf(var * (1.0f / (E_ - 1)));        // ddof=1

        float score[E_];
#pragma unroll
        for (int i = 0; i < E_; i++) score[i] = h[i] + (nz[i] - mu) / sd;

        // top-K; strict '>' = first-occurrence tie-break like jax.lax.top_k
        bool sel[E_];
#pragma unroll
        for (int i = 0; i < E_; i++) sel[i] = false;
        for (int k = 0; k < K_; k++) {
            int   best = -1;
            float bv   = -INFINITY;
#pragma unroll
            for (int i = 0; i < E_; i++) {
                if (!sel[i] && score[i] > bv) { bv = score[i]; best = i; }
            }
            sel[best] = true;
        }

        float mh = -INFINITY;
#pragma unroll
        for (int i = 0; i < E_; i++) if (sel[i]) mh = fmaxf(mh, h[i]);
        float s = 0.0f;
        float g[E_];
#pragma unroll
        for (int i = 0; i < E_; i++) {
            g[i] = sel[i] ? expf(h[i] - mh) : 0.0f;
            s += g[i];
        }
        float inv = 1.0f / s;
#pragma unroll
        for (int i = 0; i < E_; i++) out[b * E_ + i] = g[i] * inv;

        g_count[b] = 0;     // reset for next graph replay (deterministic)
    }
}

// ---------------------------------------------------------------------------
extern "C" void kernel_launch(void* const* d_in, const int* in_sizes, int n_in,
                              void* d_out, int out_size) {
    const float* x  = (const float*)d_in[0];
    const float* W0 = (const float*)d_in[1];
    const float* b0 = (const float*)d_in[2];
    const float* W1 = (const float*)d_in[3];
    const float* b1 = (const float*)d_in[4];
    float* out = (float*)d_out;

    pool_kernel<<<(B_ * C_) / ROWS_PER_BLK, 256>>>(x);

    cudaLaunchConfig_t cfg = {};
    cfg.gridDim  = dim3(B_, 1, 1);
    cfg.blockDim = dim3(512, 1, 1);
    cfg.dynamicSmemBytes = 0;
    cfg.stream = 0;
    cudaLaunchAttribute attr[1];
    attr[0].id = cudaLaunchAttributeProgrammaticStreamSerialization;
    attr[0].val.programmaticStreamSerializationAllowed = 1;
    cfg.attrs = attr;
    cfg.numAttrs = 1;
    cudaLaunchKernelEx(&cfg, gate_kernel, W0, b0, W1, b1, out);
}